// round 13
// baseline (speedup 1.0000x reference)
#include <cuda_runtime.h>
#include <cuda_fp16.h>
#include <math.h>
#include <stdint.h>

#define Nn 4096
#define Mm 4096
#define Dd 1024
#define NITER 7
#define ROWS_PB 16
#define NBLK (Nn / ROWS_PB)   // 256

#define TSCALE 67108864.0f                  // 2^26
#define TSCALE_INV 1.4901161193847656e-8f   // 2^-26
#define EPI1 0.0009765625f                  // 2^-10

// ---------------------------------------------------------------------------
// Static device scratch (no runtime allocation allowed).
// ---------------------------------------------------------------------------
static __device__ __half g_xh[(size_t)Nn * Dd];
static __device__ __half g_yh[(size_t)Mm * Dd];
static __device__ __half g_Ah[(size_t)Nn * Mm];
static __device__ __half g_K16[(size_t)Nn * Mm];
static __device__ __half g_Tth[(size_t)Mm * Nn];
static __device__ __half g_Xth[(size_t)Dd * Nn];
static __device__ float g_u[Nn];
static __device__ float g_vaccs[NITER + 1][Mm];

// ---------------------------------------------------------------------------
// PTX helpers
// ---------------------------------------------------------------------------
__device__ __forceinline__ uint32_t smem_u32(const void* p) {
    uint32_t a;
    asm("{ .reg .u64 t; cvta.to.shared.u64 t, %1; cvt.u32.u64 %0, t; }"
        : "=r"(a) : "l"(p));
    return a;
}
__device__ __forceinline__ void cp16(uint32_t saddr, const void* g) {
    asm volatile("cp.async.cg.shared.global [%0], [%1], 16;" :: "r"(saddr), "l"(g) : "memory");
}
#define CP_COMMIT() asm volatile("cp.async.commit_group;" ::: "memory")
#define CP_WAIT(n)  asm volatile("cp.async.wait_group %0;" :: "n"(n) : "memory")

__device__ __forceinline__ void ldsm_x4(uint32_t* r, uint32_t addr) {
    asm volatile("ldmatrix.sync.aligned.m8n8.x4.shared.b16 {%0,%1,%2,%3}, [%4];"
        : "=r"(r[0]), "=r"(r[1]), "=r"(r[2]), "=r"(r[3]) : "r"(addr));
}
__device__ __forceinline__ void mma_fp16(float* d, const uint32_t* a, const uint32_t* b) {
    asm volatile("mma.sync.aligned.m16n8k16.row.col.f32.f16.f16.f32 "
        "{%0,%1,%2,%3}, {%4,%5,%6,%7}, {%8,%9}, {%0,%1,%2,%3};"
        : "+f"(d[0]), "+f"(d[1]), "+f"(d[2]), "+f"(d[3])
        : "r"(a[0]), "r"(a[1]), "r"(a[2]), "r"(a[3]), "r"(b[0]), "r"(b[1]));
}

// ---------------------------------------------------------------------------
// Row L2-normalize -> fp16 (scaled x32)
// ---------------------------------------------------------------------------
__global__ void __launch_bounds__(256) normalize_rows(const float* __restrict__ in, int which) {
    int row = blockIdx.x;
    const float4* src = (const float4*)(in + (size_t)row * Dd);
    float4 val = src[threadIdx.x];
    float ss = val.x * val.x + val.y * val.y + val.z * val.z + val.w * val.w;
#pragma unroll
    for (int o = 16; o; o >>= 1) ss += __shfl_xor_sync(0xffffffffu, ss, o);
    __shared__ float wsum[8];
    int lane = threadIdx.x & 31, warp = threadIdx.x >> 5;
    if (!lane) wsum[warp] = ss;
    __syncthreads();
    float tot = 0.f;
#pragma unroll
    for (int p = 0; p < 8; p++) tot += wsum[p];
    float inv = rsqrtf(tot) * 32.0f;
    __half h[4] = {__float2half(val.x * inv), __float2half(val.y * inv),
                   __float2half(val.z * inv), __float2half(val.w * inv)};
    size_t off = (size_t)row * Dd + threadIdx.x * 4;
    *(uint2*)((which ? g_yh : g_xh) + off) = *(uint2*)h;
}

// ---------------------------------------------------------------------------
// Transpose X -> Xt fp16 (unscaled)
// ---------------------------------------------------------------------------
__global__ void __launch_bounds__(256) transpose_X(const float* __restrict__ X) {
    __shared__ float s[32][33];
    int j0 = blockIdx.x * 32;
    int i0 = blockIdx.y * 32;
    int tx = threadIdx.x & 31, ty = threadIdx.x >> 5;
#pragma unroll
    for (int r = 0; r < 4; r++)
        s[ty + r * 8][tx] = X[(size_t)(i0 + ty + r * 8) * Dd + j0 + tx];
    __syncthreads();
#pragma unroll
    for (int r = 0; r < 4; r++) {
        int orow = j0 + ty + r * 8;
        g_Xth[(size_t)orow * Nn + i0 + tx] = __float2half(s[tx][ty + r * 8]);
    }
}

// ---------------------------------------------------------------------------
// mma.sync fp16 GEMM, 256 threads, 3-stage cp.async, 2 CTAs/SM.
// MODE 0: CTA 128x128, warp grid 2x4 (warp 64x32). D = xh.yh^T -> g_Ah + g_K16
// MODE 1: CTA 128x64,  warp grid 4x2 (warp 32x32). D = Tth.Xth^T -> Cout
// Stage: TM*128 + TN*128 bytes (MODE0 32K, MODE1 24K); 3 stages each.
// ---------------------------------------------------------------------------
template <int MODE>
struct GCfg {
    static const int TM = 128;
    static const int TN = (MODE == 0) ? 128 : 64;
    static const int WGN = (MODE == 0) ? 4 : 2;     // warps along N
    static const int MT  = (MODE == 0) ? 4 : 2;     // m16 tiles per warp
    static const int STAGE = (TM + TN) * 128;       // bytes per stage
    static const int SMEM = 3 * STAGE;
};

template <int MODE>
__device__ __forceinline__ void load_stage(
    const __half* __restrict__ Ah, const __half* __restrict__ Bh,
    int ldA, int ldB, int rowA, int rowB, int k0, uint32_t sb, int tid)
{
    const int TM = GCfg<MODE>::TM, TN = GCfg<MODE>::TN;
#pragma unroll
    for (int it = 0; it < TM / 32; it++) {
        int i = tid + it * 256;
        int r = i >> 3, c = i & 7;
        uint32_t off = (uint32_t)((r << 7) | (c << 4));
        uint32_t sw = off ^ ((uint32_t)(r & 7) << 4);
        cp16(sb + sw, Ah + (size_t)(rowA + r) * ldA + k0 + c * 8);
    }
#pragma unroll
    for (int it = 0; it < TN / 32; it++) {
        int i = tid + it * 256;
        int r = i >> 3, c = i & 7;
        uint32_t off = (uint32_t)((r << 7) | (c << 4));
        uint32_t sw = off ^ ((uint32_t)(r & 7) << 4);
        cp16(sb + (uint32_t)(TM * 128) + sw, Bh + (size_t)(rowB + r) * ldB + k0 + c * 8);
    }
}

template <int MODE>
__global__ void __launch_bounds__(256, 2) gemm_wide(float* __restrict__ Cout) {
    const int TN = GCfg<MODE>::TN, WGN = GCfg<MODE>::WGN, MT = GCfg<MODE>::MT;
    const int STAGE = GCfg<MODE>::STAGE;
    extern __shared__ char smem[];
    uint32_t sbase = smem_u32(smem);
    int tid = threadIdx.x;
    int lane = tid & 31, wid = tid >> 5;
    int wm = wid / WGN, wn = wid % WGN;

    const __half *Ah, *Bh;
    int K, ldA, ldB;
    if (MODE == 0) { Ah = g_xh;  Bh = g_yh;  K = Dd; ldA = Dd; ldB = Dd; }
    else           { Ah = g_Tth; Bh = g_Xth; K = Nn; ldA = Nn; ldB = Nn; }

    int bm = blockIdx.y, bn = blockIdx.x;
    int rowA = bm * 128, rowB = bn * TN;

    float acc[MT][4][4];
#pragma unroll
    for (int a = 0; a < MT; a++)
#pragma unroll
        for (int b = 0; b < 4; b++)
#pragma unroll
            for (int c = 0; c < 4; c++) acc[a][b][c] = 0.f;

    int arow = wm * (MT * 16) + (lane & 7) + 8 * ((lane >> 3) & 1);
    uint32_t akb = 16u * (lane >> 4);
    uint32_t xorA = (uint32_t)(arow & 7) << 4;
    uint32_t aRB = (uint32_t)arow << 7;
    int browl = (lane & 7) + 8 * (lane >> 4);
    uint32_t bkb = 16u * ((lane >> 3) & 1);
    uint32_t xorB = (uint32_t)(lane & 7) << 4;

    const int NT = K / 64;

    load_stage<MODE>(Ah, Bh, ldA, ldB, rowA, rowB, 0, sbase, tid);
    CP_COMMIT();
    load_stage<MODE>(Ah, Bh, ldA, ldB, rowA, rowB, 64, sbase + STAGE, tid);
    CP_COMMIT();

    for (int kt = 0; kt < NT; kt++) {
        if (kt + 2 < NT) { CP_WAIT(1); } else { CP_WAIT(0); }
        __syncthreads();
        if (kt + 2 < NT) {
            load_stage<MODE>(Ah, Bh, ldA, ldB, rowA, rowB, (kt + 2) * 64,
                             sbase + (uint32_t)((kt + 2) % 3) * STAGE, tid);
            CP_COMMIT();
        }
        uint32_t sb = sbase + (uint32_t)(kt % 3) * STAGE;
        uint32_t sAh = sb, sBh = sb + (uint32_t)(GCfg<MODE>::TM * 128);
#pragma unroll
        for (int ks = 0; ks < 4; ks++) {
            uint32_t ca = (akb + 32u * ks) ^ xorA;
            uint32_t cb = (bkb + 32u * ks) ^ xorB;
            uint32_t fA[MT][4], fB[2][4];
#pragma unroll
            for (int mt = 0; mt < MT; mt++)
                ldsm_x4(fA[mt], sAh + aRB + (uint32_t)mt * 2048 + ca);
#pragma unroll
            for (int nt2 = 0; nt2 < 2; nt2++)
                ldsm_x4(fB[nt2], sBh + ((uint32_t)(wn * 32 + nt2 * 16 + browl) << 7) + cb);
#pragma unroll
            for (int nt2 = 0; nt2 < 2; nt2++)
#pragma unroll
                for (int mt = 0; mt < MT; mt++) {
                    mma_fp16(acc[mt][2 * nt2],     fA[mt], &fB[nt2][0]);
                    mma_fp16(acc[mt][2 * nt2 + 1], fA[mt], &fB[nt2][2]);
                }
        }
    }

    int r0 = bm * 128 + wm * (MT * 16) + (lane >> 2);
    int c0 = bn * TN + wn * 32 + (lane & 3) * 2;
#pragma unroll
    for (int mt = 0; mt < MT; mt++)
#pragma unroll
        for (int half = 0; half < 2; half++) {
            int row = r0 + mt * 16 + half * 8;
            if (MODE == 0) {
                size_t base = (size_t)row * Mm;
#pragma unroll
                for (int nt = 0; nt < 4; nt++) {
                    float d0 = acc[mt][nt][half * 2 + 0] * EPI1;
                    float d1 = acc[mt][nt][half * 2 + 1] * EPI1;
                    int col = c0 + nt * 8;
                    *(__half2*)&g_Ah[base + col] = __floats2half2_rn(d0, d1);
                    *(__half2*)&g_K16[base + col] = __floats2half2_rn(expf(d0), expf(d1));
                }
            } else {
                size_t base = (size_t)row * Dd;
#pragma unroll
                for (int nt = 0; nt < 4; nt++) {
                    int col = c0 + nt * 8;
                    *(float2*)&Cout[base + col] =
                        make_float2(acc[mt][nt][half * 2 + 0] * TSCALE_INV,
                                    acc[mt][nt][half * 2 + 1] * TSCALE_INV);
                }
            }
        }
}

// ---------------------------------------------------------------------------
// init: vacc buffers. v_j(it) = sqrt(b / vacc[it][j]); vacc[0]=4096 -> v0=1/4096
// ---------------------------------------------------------------------------
__global__ void init_sink() {
    int i = blockIdx.x * 256 + threadIdx.x;
    g_vaccs[0][i] = 4096.0f;
#pragma unroll
    for (int k = 1; k <= NITER; k++) g_vaccs[k][i] = 0.f;
}

// ---------------------------------------------------------------------------
// Sinkhorn iteration: ONE kernel. 256 blocks x 512 threads, 16 rows/block
// (multiple blocks resident per SM; full chip coverage).
// ---------------------------------------------------------------------------
__global__ void __launch_bounds__(512) sink_iter(int it) {
    __shared__ float vsh[Mm];      // 16 KB
    __shared__ float ush[ROWS_PB];
    int tid = threadIdx.x;
    int warp = tid >> 5, lane = tid & 31;   // 16 warps
    int row0 = blockIdx.x * ROWS_PB;

    const float* vacc = g_vaccs[it];
    float* vnext = g_vaccs[it + 1];

    for (int j = tid; j < Mm; j += 512)
        vsh[j] = sqrtf((1.0f / Mm) / vacc[j]);
    __syncthreads();

    // Phase 1: each warp handles one row
    {
        const uint4* Kr = (const uint4*)(g_K16 + (size_t)(row0 + warp) * Mm);
        float acc = 0.f;
#pragma unroll 4
        for (int j = lane; j < Mm / 8; j += 32) {
            uint4 kq = Kr[j];
            float4 va = *(const float4*)&vsh[j * 8];
            float4 vb = *(const float4*)&vsh[j * 8 + 4];
            float2 k0 = __half22float2(*(__half2*)&kq.x);
            float2 k1 = __half22float2(*(__half2*)&kq.y);
            float2 k2 = __half22float2(*(__half2*)&kq.z);
            float2 k3 = __half22float2(*(__half2*)&kq.w);
            acc += k0.x * va.x + k0.y * va.y + k1.x * va.z + k1.y * va.w
                 + k2.x * vb.x + k2.y * vb.y + k3.x * vb.z + k3.y * vb.w;
        }
#pragma unroll
        for (int o = 16; o; o >>= 1) acc += __shfl_xor_sync(0xffffffffu, acc, o);
        if (!lane) {
            float u = sqrtf((1.0f / Nn) / acc);
            ush[warp] = u;
            g_u[row0 + warp] = u;
        }
    }
    __syncthreads();

    // Phase 2: column partials over this block's 16-row slice
#pragma unroll
    for (int t = 0; t < 4; t++) {
        int j = tid * 2 + t * 1024;
        float ax = 0.f, ay = 0.f;
#pragma unroll
        for (int i = 0; i < ROWS_PB; i++) {
            __half2 kk = *(const __half2*)(g_K16 + (size_t)(row0 + i) * Mm + j);
            float2 kf = __half22float2(kk);
            float u = ush[i];
            ax += kf.x * u;
            ay += kf.y * u;
        }
        atomicAdd(&vnext[j], ax);
        atomicAdd(&vnext[j + 1], ay);
    }
}

// ---------------------------------------------------------------------------
// finalize: T = A*u*exp(A)*v (fp32 -> d_out), plus Tt fp16 (x2^26, transposed)
// ---------------------------------------------------------------------------
__global__ void __launch_bounds__(256) finalize_T(float* __restrict__ T) {
    __shared__ float s[32][33];
    int j0 = blockIdx.x * 32, i0 = blockIdx.y * 32;
    int tx = threadIdx.x & 31, ty = threadIdx.x >> 5;
    float vj = sqrtf((1.0f / Mm) / g_vaccs[NITER][j0 + tx]);
#pragma unroll
    for (int r = 0; r < 4; r++) {
        int row = i0 + ty + r * 8;
        float a = __half2float(g_Ah[(size_t)row * Mm + j0 + tx]);
        float t = a * g_u[row] * expf(a) * vj;
        T[(size_t)row * Mm + j0 + tx] = t;
        s[ty + r * 8][tx] = t;
    }
    __syncthreads();
#pragma unroll
    for (int r = 0; r < 4; r++) {
        int orow = j0 + ty + r * 8;
        g_Tth[(size_t)orow * Nn + i0 + tx] = __float2half(s[tx][ty + r * 8] * TSCALE);
    }
}

// ---------------------------------------------------------------------------
extern "C" void kernel_launch(void* const* d_in, const int* in_sizes, int n_in,
                              void* d_out, int out_size) {
    const float* X = (const float*)d_in[0];
    const float* Y = (const float*)d_in[1];
    float* out = (float*)d_out;
    float* aligned = out;                          // [4096,1024]
    float* Tmat = out + (size_t)Mm * Dd;           // [4096,4096]

    cudaFuncSetAttribute(gemm_wide<0>, cudaFuncAttributeMaxDynamicSharedMemorySize, GCfg<0>::SMEM);
    cudaFuncSetAttribute(gemm_wide<1>, cudaFuncAttributeMaxDynamicSharedMemorySize, GCfg<1>::SMEM);

    normalize_rows<<<Nn, 256>>>(X, 0);
    normalize_rows<<<Mm, 256>>>(Y, 1);
    transpose_X<<<dim3(Dd / 32, Nn / 32), 256>>>(X);

    gemm_wide<0><<<dim3(Mm / 128, Nn / 128), 256, GCfg<0>::SMEM>>>(nullptr);

    init_sink<<<Mm / 256, 256>>>();
    for (int it = 0; it < NITER; it++)
        sink_iter<<<NBLK, 512>>>(it);

    finalize_T<<<dim3(Mm / 32, Nn / 32), 256>>>(Tmat);

    gemm_wide<1><<<dim3(Dd / 64, Mm / 128), 256, GCfg<1>::SMEM>>>(aligned);
}

// round 14
// speedup vs baseline: 1.0325x; 1.0325x over previous
#include <cuda_runtime.h>
#include <cuda_fp16.h>
#include <math.h>
#include <stdint.h>

#define Nn 4096
#define Mm 4096
#define Dd 1024
#define NITER 7
#define ROWS_PB 16
#define NBLK (Nn / ROWS_PB)   // 256

#define TSCALE 67108864.0f                  // 2^26
#define TSCALE_INV 1.4901161193847656e-8f   // 2^-26
#define EPI1 0.0009765625f                  // 2^-10

// ---------------------------------------------------------------------------
// Static device scratch (no runtime allocation allowed).
// ---------------------------------------------------------------------------
static __device__ __half g_xh[(size_t)Nn * Dd];
static __device__ __half g_yh[(size_t)Mm * Dd];
static __device__ __half g_Ah[(size_t)Nn * Mm];
static __device__ __half g_K16[(size_t)Nn * Mm];
static __device__ __half g_Tth[(size_t)Mm * Nn];
static __device__ __half g_Xth[(size_t)Dd * Nn];
static __device__ float g_u[Nn];
static __device__ float g_vaccs[NITER + 1][Mm];

// ---------------------------------------------------------------------------
// PTX helpers
// ---------------------------------------------------------------------------
__device__ __forceinline__ uint32_t smem_u32(const void* p) {
    uint32_t a;
    asm("{ .reg .u64 t; cvta.to.shared.u64 t, %1; cvt.u32.u64 %0, t; }"
        : "=r"(a) : "l"(p));
    return a;
}
__device__ __forceinline__ void cp16(uint32_t saddr, const void* g) {
    asm volatile("cp.async.cg.shared.global [%0], [%1], 16;" :: "r"(saddr), "l"(g) : "memory");
}
#define CP_COMMIT() asm volatile("cp.async.commit_group;" ::: "memory")
#define CP_WAIT(n)  asm volatile("cp.async.wait_group %0;" :: "n"(n) : "memory")

__device__ __forceinline__ void ldsm_x4(uint32_t* r, uint32_t addr) {
    asm volatile("ldmatrix.sync.aligned.m8n8.x4.shared.b16 {%0,%1,%2,%3}, [%4];"
        : "=r"(r[0]), "=r"(r[1]), "=r"(r[2]), "=r"(r[3]) : "r"(addr));
}
__device__ __forceinline__ void mma_fp16(float* d, const uint32_t* a, const uint32_t* b) {
    asm volatile("mma.sync.aligned.m16n8k16.row.col.f32.f16.f16.f32 "
        "{%0,%1,%2,%3}, {%4,%5,%6,%7}, {%8,%9}, {%0,%1,%2,%3};"
        : "+f"(d[0]), "+f"(d[1]), "+f"(d[2]), "+f"(d[3])
        : "r"(a[0]), "r"(a[1]), "r"(a[2]), "r"(a[3]), "r"(b[0]), "r"(b[1]));
}

// ---------------------------------------------------------------------------
// Row L2-normalize -> fp16 (scaled x32)
// ---------------------------------------------------------------------------
__global__ void __launch_bounds__(256) normalize_rows(const float* __restrict__ in, int which) {
    int row = blockIdx.x;
    const float4* src = (const float4*)(in + (size_t)row * Dd);
    float4 val = src[threadIdx.x];
    float ss = val.x * val.x + val.y * val.y + val.z * val.z + val.w * val.w;
#pragma unroll
    for (int o = 16; o; o >>= 1) ss += __shfl_xor_sync(0xffffffffu, ss, o);
    __shared__ float wsum[8];
    int lane = threadIdx.x & 31, warp = threadIdx.x >> 5;
    if (!lane) wsum[warp] = ss;
    __syncthreads();
    float tot = 0.f;
#pragma unroll
    for (int p = 0; p < 8; p++) tot += wsum[p];
    float inv = rsqrtf(tot) * 32.0f;
    __half h[4] = {__float2half(val.x * inv), __float2half(val.y * inv),
                   __float2half(val.z * inv), __float2half(val.w * inv)};
    size_t off = (size_t)row * Dd + threadIdx.x * 4;
    *(uint2*)((which ? g_yh : g_xh) + off) = *(uint2*)h;
}

// ---------------------------------------------------------------------------
// Transpose X -> Xt fp16 (unscaled)
// ---------------------------------------------------------------------------
__global__ void __launch_bounds__(256) transpose_X(const float* __restrict__ X) {
    __shared__ float s[32][33];
    int j0 = blockIdx.x * 32;
    int i0 = blockIdx.y * 32;
    int tx = threadIdx.x & 31, ty = threadIdx.x >> 5;
#pragma unroll
    for (int r = 0; r < 4; r++)
        s[ty + r * 8][tx] = X[(size_t)(i0 + ty + r * 8) * Dd + j0 + tx];
    __syncthreads();
#pragma unroll
    for (int r = 0; r < 4; r++) {
        int orow = j0 + ty + r * 8;
        g_Xth[(size_t)orow * Nn + i0 + tx] = __float2half(s[tx][ty + r * 8]);
    }
}

// ---------------------------------------------------------------------------
// mma.sync fp16 GEMM: 256 threads, CTA 128x128, warp grid 2x4 (warp 64x32),
// BK=64, 3-stage cp.async, 2 CTAs/SM, k-ring STAGGERED by CTA parity so the
// two co-resident CTAs' load/compute phases interleave.
// MODE 0: D = xh.yh^T -> g_Ah (fp16 x2^-10) + g_K16 (fp16 exp)
// MODE 1: D = Tth.Xth^T -> Cout (x2^-26)
// Stage = [A 16K][B 16K] = 32K; x3 = 96K -> 2 CTAs/SM.
// ---------------------------------------------------------------------------
#define TILE_A 16384
#define STAGE_B6 32768
#define GEMM_SMEM (3 * STAGE_B6)

template <int MODE>
__device__ __forceinline__ void load_stage(
    const __half* __restrict__ Ah, const __half* __restrict__ Bh,
    int ldA, int ldB, int rowA, int rowB, int k0, uint32_t sb, int tid)
{
#pragma unroll
    for (int it = 0; it < 4; it++) {
        int i = tid + it * 256;
        int r = i >> 3, c = i & 7;
        uint32_t off = (uint32_t)((r << 7) | (c << 4));
        uint32_t sw = off ^ ((uint32_t)(r & 7) << 4);
        cp16(sb + sw, Ah + (size_t)(rowA + r) * ldA + k0 + c * 8);
    }
#pragma unroll
    for (int it = 0; it < 4; it++) {
        int i = tid + it * 256;
        int r = i >> 3, c = i & 7;
        uint32_t off = (uint32_t)((r << 7) | (c << 4));
        uint32_t sw = off ^ ((uint32_t)(r & 7) << 4);
        cp16(sb + TILE_A + sw, Bh + (size_t)(rowB + r) * ldB + k0 + c * 8);
    }
}

template <int MODE>
__global__ void __launch_bounds__(256, 2) gemm_wide(float* __restrict__ Cout) {
    extern __shared__ char smem[];
    uint32_t sbase = smem_u32(smem);
    int tid = threadIdx.x;
    int lane = tid & 31, wid = tid >> 5;
    int wm = wid >> 2, wn = wid & 3;      // 2 x 4 warps -> warp tile 64 x 32

    const __half *Ah, *Bh;
    int K, ldA, ldB;
    if (MODE == 0) { Ah = g_xh;  Bh = g_yh;  K = Dd; ldA = Dd; ldB = Dd; }
    else           { Ah = g_Tth; Bh = g_Xth; K = Nn; ldA = Nn; ldB = Nn; }

    int bm = blockIdx.y, bn = blockIdx.x;
    int rowA = bm * 128, rowB = bn * 128;

    float acc[4][4][4];
#pragma unroll
    for (int a = 0; a < 4; a++)
#pragma unroll
        for (int b = 0; b < 4; b++)
#pragma unroll
            for (int c = 0; c < 4; c++) acc[a][b][c] = 0.f;

    int arow = wm * 64 + (lane & 7) + 8 * ((lane >> 3) & 1);
    uint32_t akb = 16u * (lane >> 4);
    uint32_t xorA = (uint32_t)(arow & 7) << 4;
    uint32_t aRB = (uint32_t)arow << 7;
    int browl = (lane & 7) + 8 * (lane >> 4);
    uint32_t bkb = 16u * ((lane >> 3) & 1);
    uint32_t xorB = (uint32_t)(lane & 7) << 4;

    const int NT = K / 64;
    // Stagger: odd CTAs start their K ring halfway around (fp32 reassociation only)
    int koff = ((bn + bm) & 1) * (NT / 2);

    load_stage<MODE>(Ah, Bh, ldA, ldB, rowA, rowB, koff * 64, sbase, tid);
    CP_COMMIT();
    load_stage<MODE>(Ah, Bh, ldA, ldB, rowA, rowB, ((koff + 1) % NT) * 64, sbase + STAGE_B6, tid);
    CP_COMMIT();

    for (int kt = 0; kt < NT; kt++) {
        if (kt + 2 < NT) { CP_WAIT(1); } else { CP_WAIT(0); }
        __syncthreads();
        if (kt + 2 < NT) {
            int klog = (kt + 2 + koff) % NT;
            load_stage<MODE>(Ah, Bh, ldA, ldB, rowA, rowB, klog * 64,
                             sbase + (uint32_t)((kt + 2) % 3) * STAGE_B6, tid);
            CP_COMMIT();
        }
        uint32_t sb = sbase + (uint32_t)(kt % 3) * STAGE_B6;
        uint32_t sAh = sb, sBh = sb + TILE_A;
#pragma unroll
        for (int ks = 0; ks < 4; ks++) {
            uint32_t ca = (akb + 32u * ks) ^ xorA;
            uint32_t cb = (bkb + 32u * ks) ^ xorB;
            uint32_t fA[4][4], fB[2][4];
#pragma unroll
            for (int mt = 0; mt < 4; mt++)
                ldsm_x4(fA[mt], sAh + aRB + (uint32_t)mt * 2048 + ca);
#pragma unroll
            for (int nt2 = 0; nt2 < 2; nt2++)
                ldsm_x4(fB[nt2], sBh + ((uint32_t)(wn * 32 + nt2 * 16 + browl) << 7) + cb);
#pragma unroll
            for (int nt2 = 0; nt2 < 2; nt2++)
#pragma unroll
                for (int mt = 0; mt < 4; mt++) {
                    mma_fp16(acc[mt][2 * nt2],     fA[mt], &fB[nt2][0]);
                    mma_fp16(acc[mt][2 * nt2 + 1], fA[mt], &fB[nt2][2]);
                }
        }
    }

    int r0 = bm * 128 + wm * 64 + (lane >> 2);
    int c0 = bn * 128 + wn * 32 + (lane & 3) * 2;
#pragma unroll
    for (int mt = 0; mt < 4; mt++)
#pragma unroll
        for (int half = 0; half < 2; half++) {
            int row = r0 + mt * 16 + half * 8;
            if (MODE == 0) {
                size_t base = (size_t)row * Mm;
#pragma unroll
                for (int nt = 0; nt < 4; nt++) {
                    float d0 = acc[mt][nt][half * 2 + 0] * EPI1;
                    float d1 = acc[mt][nt][half * 2 + 1] * EPI1;
                    int col = c0 + nt * 8;
                    *(__half2*)&g_Ah[base + col] = __floats2half2_rn(d0, d1);
                    *(__half2*)&g_K16[base + col] = __floats2half2_rn(expf(d0), expf(d1));
                }
            } else {
                size_t base = (size_t)row * Dd;
#pragma unroll
                for (int nt = 0; nt < 4; nt++) {
                    int col = c0 + nt * 8;
                    *(float2*)&Cout[base + col] =
                        make_float2(acc[mt][nt][half * 2 + 0] * TSCALE_INV,
                                    acc[mt][nt][half * 2 + 1] * TSCALE_INV);
                }
            }
        }
}

// ---------------------------------------------------------------------------
// init: vacc buffers. v_j(it) = sqrt(b / vacc[it][j]); vacc[0]=4096 -> v0=1/4096
// ---------------------------------------------------------------------------
__global__ void init_sink() {
    int i = blockIdx.x * 256 + threadIdx.x;
    g_vaccs[0][i] = 4096.0f;
#pragma unroll
    for (int k = 1; k <= NITER; k++) g_vaccs[k][i] = 0.f;
}

// ---------------------------------------------------------------------------
// Sinkhorn iteration: ONE kernel. 256 blocks x 512 threads, 16 rows/block.
// ---------------------------------------------------------------------------
__global__ void __launch_bounds__(512) sink_iter(int it) {
    __shared__ float vsh[Mm];      // 16 KB
    __shared__ float ush[ROWS_PB];
    int tid = threadIdx.x;
    int warp = tid >> 5, lane = tid & 31;   // 16 warps
    int row0 = blockIdx.x * ROWS_PB;

    const float* vacc = g_vaccs[it];
    float* vnext = g_vaccs[it + 1];

    for (int j = tid; j < Mm; j += 512)
        vsh[j] = sqrtf((1.0f / Mm) / vacc[j]);
    __syncthreads();

    // Phase 1: each warp handles one row
    {
        const uint4* Kr = (const uint4*)(g_K16 + (size_t)(row0 + warp) * Mm);
        float acc = 0.f;
#pragma unroll 4
        for (int j = lane; j < Mm / 8; j += 32) {
            uint4 kq = Kr[j];
            float4 va = *(const float4*)&vsh[j * 8];
            float4 vb = *(const float4*)&vsh[j * 8 + 4];
            float2 k0 = __half22float2(*(__half2*)&kq.x);
            float2 k1 = __half22float2(*(__half2*)&kq.y);
            float2 k2 = __half22float2(*(__half2*)&kq.z);
            float2 k3 = __half22float2(*(__half2*)&kq.w);
            acc += k0.x * va.x + k0.y * va.y + k1.x * va.z + k1.y * va.w
                 + k2.x * vb.x + k2.y * vb.y + k3.x * vb.z + k3.y * vb.w;
        }
#pragma unroll
        for (int o = 16; o; o >>= 1) acc += __shfl_xor_sync(0xffffffffu, acc, o);
        if (!lane) {
            float u = sqrtf((1.0f / Nn) / acc);
            ush[warp] = u;
            g_u[row0 + warp] = u;
        }
    }
    __syncthreads();

    // Phase 2: column partials over this block's 16-row slice
#pragma unroll
    for (int t = 0; t < 4; t++) {
        int j = tid * 2 + t * 1024;
        float ax = 0.f, ay = 0.f;
#pragma unroll
        for (int i = 0; i < ROWS_PB; i++) {
            __half2 kk = *(const __half2*)(g_K16 + (size_t)(row0 + i) * Mm + j);
            float2 kf = __half22float2(kk);
            float u = ush[i];
            ax += kf.x * u;
            ay += kf.y * u;
        }
        atomicAdd(&vnext[j], ax);
        atomicAdd(&vnext[j + 1], ay);
    }
}

// ---------------------------------------------------------------------------
// finalize: T = A*u*exp(A)*v (fp32 -> d_out), plus Tt fp16 (x2^26, transposed)
// ---------------------------------------------------------------------------
__global__ void __launch_bounds__(256) finalize_T(float* __restrict__ T) {
    __shared__ float s[32][33];
    int j0 = blockIdx.x * 32, i0 = blockIdx.y * 32;
    int tx = threadIdx.x & 31, ty = threadIdx.x >> 5;
    float vj = sqrtf((1.0f / Mm) / g_vaccs[NITER][j0 + tx]);
#pragma unroll
    for (int r = 0; r < 4; r++) {
        int row = i0 + ty + r * 8;
        float a = __half2float(g_Ah[(size_t)row * Mm + j0 + tx]);
        float t = a * g_u[row] * expf(a) * vj;
        T[(size_t)row * Mm + j0 + tx] = t;
        s[ty + r * 8][tx] = t;
    }
    __syncthreads();
#pragma unroll
    for (int r = 0; r < 4; r++) {
        int orow = j0 + ty + r * 8;
        g_Tth[(size_t)orow * Nn + i0 + tx] = __float2half(s[tx][ty + r * 8] * TSCALE);
    }
}

// ---------------------------------------------------------------------------
extern "C" void kernel_launch(void* const* d_in, const int* in_sizes, int n_in,
                              void* d_out, int out_size) {
    const float* X = (const float*)d_in[0];
    const float* Y = (const float*)d_in[1];
    float* out = (float*)d_out;
    float* aligned = out;                          // [4096,1024]
    float* Tmat = out + (size_t)Mm * Dd;           // [4096,4096]

    cudaFuncSetAttribute(gemm_wide<0>, cudaFuncAttributeMaxDynamicSharedMemorySize, GEMM_SMEM);
    cudaFuncSetAttribute(gemm_wide<1>, cudaFuncAttributeMaxDynamicSharedMemorySize, GEMM_SMEM);

    normalize_rows<<<Nn, 256>>>(X, 0);
    normalize_rows<<<Mm, 256>>>(Y, 1);
    transpose_X<<<dim3(Dd / 32, Nn / 32), 256>>>(X);

    gemm_wide<0><<<dim3(Mm / 128, Nn / 128), 256, GEMM_SMEM>>>(nullptr);

    init_sink<<<Mm / 256, 256>>>();
    for (int it = 0; it < NITER; it++)
        sink_iter<<<NBLK, 512>>>(it);

    finalize_T<<<dim3(Mm / 32, Nn / 32), 256>>>(Tmat);

    gemm_wide<1><<<dim3(Dd / 128, Mm / 128), 256, GEMM_SMEM>>>(aligned);
}